// round 1
// baseline (speedup 1.0000x reference)
#include <cuda_runtime.h>

// ---------------- problem dimensions (fixed) ----------------
#define N2v 131072
#define N3v 32768
#define N4v 8192
#define N5v 2048
#define D2v 256
#define D3v 512
#define D4v 1024
#define D5v 2048
#define C_IN 2048   // inproj output
#define C4v 1024
#define C3v 512
#define COUTv 256
#define K1v 2048
#define K4v 3072
#define K3v 1536
#define K2v 768
#define NEG_SLOPE 0.1f
#define GN_EPS 1e-5f

// ---------------- scratch (static device globals; no allocs) ----------------
__device__ float g_x5[(size_t)N5v * C_IN];          //  16 MB
__device__ float g_l4in[(size_t)N4v * K4v];          // 100 MB
__device__ float g_y4[(size_t)N4v * C4v];            //  33 MB
__device__ float g_l3in[(size_t)N3v * K3v];          // 201 MB
__device__ float g_y3[(size_t)N3v * C3v];            //  67 MB
__device__ float g_l2in[(size_t)N2v * K2v];          // 402 MB
__device__ float g_stats[128];   // sum4[32], ss4[32], sum3[32], ss3[32]
__device__ float g_gn[128];      // mean4[32], inv4[32], mean3[32], inv3[32]

// ---------------- init: zero stats accumulators ----------------
__global__ void init_stats_kernel() {
    if (threadIdx.x < 128) g_stats[threadIdx.x] = 0.0f;
}

// ---------------- GEMM: C(N,M) = A(N,K) @ W(M,K)^T + bias ----------------
// 128x128 block tile, BK=16, 256 threads, 8x8 micro-tile per thread.
// Optional fused GroupNorm statistics (sum, sumsq) accumulation per group.
template<int DO_STATS>
__global__ void __launch_bounds__(256)
gemm_kernel(const float* __restrict__ A, const float* __restrict__ W,
            const float* __restrict__ bias, float* __restrict__ C,
            int K, int M,
            float* __restrict__ gsum, float* __restrict__ gss, int chPerGroup)
{
    const int BM = 128, BN = 128, BK = 16;
    __shared__ float As[BK][BM + 4];
    __shared__ float Ws[BK][BN + 4];

    const int tid = threadIdx.x;
    const int tx = tid & 15;        // 0..15 -> column micro-tile
    const int ty = tid >> 4;        // 0..15 -> row micro-tile
    const long rBase = (long)blockIdx.y * BM;
    const long cBase = (long)blockIdx.x * BN;

    float acc[8][8];
#pragma unroll
    for (int i = 0; i < 8; i++)
#pragma unroll
        for (int j = 0; j < 8; j++) acc[i][j] = 0.0f;

    const float* Aptr = A + rBase * K;
    const float* Wptr = W + cBase * K;

    for (int k0 = 0; k0 < K; k0 += BK) {
        // cooperative load + transpose into k-major smem
#pragma unroll
        for (int j = 0; j < 2; j++) {
            int idx = tid + j * 256;     // 0..511 (512 float4 per tile)
            int row = idx >> 2;          // 0..127
            int kq  = idx & 3;           // float4 slot within 16-wide K chunk
            float4 va = *(const float4*)(Aptr + (long)row * K + k0 + kq * 4);
            As[kq * 4 + 0][row] = va.x;
            As[kq * 4 + 1][row] = va.y;
            As[kq * 4 + 2][row] = va.z;
            As[kq * 4 + 3][row] = va.w;
            float4 vw = *(const float4*)(Wptr + (long)row * K + k0 + kq * 4);
            Ws[kq * 4 + 0][row] = vw.x;
            Ws[kq * 4 + 1][row] = vw.y;
            Ws[kq * 4 + 2][row] = vw.z;
            Ws[kq * 4 + 3][row] = vw.w;
        }
        __syncthreads();
#pragma unroll
        for (int kk = 0; kk < BK; kk++) {
            float a[8], b[8];
            *(float4*)(a)     = *(const float4*)&As[kk][ty * 8];
            *(float4*)(a + 4) = *(const float4*)&As[kk][ty * 8 + 4];
            *(float4*)(b)     = *(const float4*)&Ws[kk][tx * 8];
            *(float4*)(b + 4) = *(const float4*)&Ws[kk][tx * 8 + 4];
#pragma unroll
            for (int i = 0; i < 8; i++)
#pragma unroll
                for (int j = 0; j < 8; j++) acc[i][j] += a[i] * b[j];
        }
        __syncthreads();
    }

    // epilogue: add bias, store, optionally accumulate GN stats
    float bcol[8];
#pragma unroll
    for (int j = 0; j < 8; j++) bcol[j] = bias[cBase + tx * 8 + j];

    float s = 0.0f, ss = 0.0f;
#pragma unroll
    for (int i = 0; i < 8; i++) {
        long row = rBase + ty * 8 + i;
        float* Crow = C + row * M + cBase + tx * 8;
        float v[8];
#pragma unroll
        for (int j = 0; j < 8; j++) {
            v[j] = acc[i][j] + bcol[j];
            if (DO_STATS) { s += v[j]; ss += v[j] * v[j]; }
        }
        *(float4*)(Crow)     = make_float4(v[0], v[1], v[2], v[3]);
        *(float4*)(Crow + 4) = make_float4(v[4], v[5], v[6], v[7]);
    }

    if (DO_STATS) {
        __shared__ float bs[8], bss[8];
        if (tid < 8) { bs[tid] = 0.0f; bss[tid] = 0.0f; }
        __syncthreads();
        int gLocal = (tx * 8) / chPerGroup;   // each 8-col strip lies in one group
        atomicAdd(&bs[gLocal], s);
        atomicAdd(&bss[gLocal], ss);
        __syncthreads();
        int gpb = BN / chPerGroup;            // groups per block (4 or 8)
        if (tid < gpb) {
            int g = (int)(cBase / chPerGroup) + tid;
            atomicAdd(&gsum[g], bs[tid]);
            atomicAdd(&gss[g],  bss[tid]);
        }
    }
}

// ---------------- GN finalize: mean & inv-std per group ----------------
__global__ void gn_finalize_kernel(int which) {
    int g = threadIdx.x;  // 0..31
    if (g >= 32) return;
    if (which == 0) {
        float cnt = (float)((C4v / 32) * N4v);       // 32ch * 8192 rows
        float m = g_stats[g] / cnt;
        float var = g_stats[32 + g] / cnt - m * m;
        g_gn[g] = m;
        g_gn[32 + g] = rsqrtf(var + GN_EPS);
    } else {
        float cnt = (float)((C3v / 32) * N3v);       // 16ch * 32768 rows
        float m = g_stats[64 + g] / cnt;
        float var = g_stats[96 + g] / cnt - m * m;
        g_gn[64 + g] = m;
        g_gn[96 + g] = rsqrtf(var + GN_EPS);
    }
}

// ---------------- gather + concat (no activation, for level 4 input) ----------------
__global__ void concat4_kernel(const float* __restrict__ x5,
                               const int* __restrict__ up3,
                               const float* __restrict__ f4,
                               float* __restrict__ out)
{
    int r = blockIdx.x;
    int src = up3[r];
    const float4* a = (const float4*)(x5 + (long)src * C_IN);
    const float4* b = (const float4*)(f4 + (long)r * D4v);
    float4* o = (float4*)(out + (long)r * K4v);
    const int QA = C_IN / 4, QT = K4v / 4;
    for (int c = threadIdx.x; c < QT; c += blockDim.x)
        o[c] = (c < QA) ? a[c] : b[c - QA];
}

// ---------------- gather + GN-normalize + LeakyReLU + concat ----------------
__global__ void concat_act_kernel(const float* __restrict__ y,
                                  const int* __restrict__ up,
                                  const float* __restrict__ f,
                                  float* __restrict__ out,
                                  const float* __restrict__ gamma,
                                  const float* __restrict__ beta,
                                  const float* __restrict__ gnMean,
                                  const float* __restrict__ gnInv,
                                  int Cy, int Cf, int chPerGroup)
{
    int r = blockIdx.x;
    int src = up[r];
    int Ktot = Cy + Cf;
    const float* yrow = y + (long)src * Cy;
    const float* frow = f + (long)r * Cf;
    float* orow = out + (long)r * Ktot;
    for (int c4 = threadIdx.x; c4 < Ktot / 4; c4 += blockDim.x) {
        int c = c4 * 4;
        float4 v;
        if (c < Cy) {
            v = *(const float4*)(yrow + c);
            int g = c / chPerGroup;             // 4 consecutive channels share a group
            float m = gnMean[g], inv = gnInv[g];
            float vals[4] = {v.x, v.y, v.z, v.w};
#pragma unroll
            for (int t = 0; t < 4; t++) {
                float u = (vals[t] - m) * inv * gamma[c + t] + beta[c + t];
                vals[t] = (u > 0.0f) ? u : u * NEG_SLOPE;
            }
            v = make_float4(vals[0], vals[1], vals[2], vals[3]);
        } else {
            v = *(const float4*)(frow + (c - Cy));
        }
        *(float4*)(orow + c) = v;
    }
}

// ---------------- launch ----------------
extern "C" void kernel_launch(void* const* d_in, const int* in_sizes, int n_in,
                              void* d_out, int out_size)
{
    (void)in_sizes; (void)n_in; (void)out_size;
    const float* feats_s2 = (const float*)d_in[0];
    const float* feats_s3 = (const float*)d_in[1];
    const float* feats_s4 = (const float*)d_in[2];
    const float* feats_s5 = (const float*)d_in[3];
    const int*   up1      = (const int*)d_in[4];
    const int*   up2      = (const int*)d_in[5];
    const int*   up3      = (const int*)d_in[6];
    const float* W_in     = (const float*)d_in[7];
    const float* b_in     = (const float*)d_in[8];
    const float* W4       = (const float*)d_in[9];
    const float* b4       = (const float*)d_in[10];
    const float* g4       = (const float*)d_in[11];
    const float* beta4    = (const float*)d_in[12];
    const float* W3       = (const float*)d_in[13];
    const float* b3       = (const float*)d_in[14];
    const float* g3       = (const float*)d_in[15];
    const float* beta3    = (const float*)d_in[16];
    const float* W2       = (const float*)d_in[17];
    const float* b2       = (const float*)d_in[18];
    float* out = (float*)d_out;

    void *p_x5, *p_l4in, *p_y4, *p_l3in, *p_y3, *p_l2in, *p_stats, *p_gn;
    cudaGetSymbolAddress(&p_x5,    g_x5);
    cudaGetSymbolAddress(&p_l4in,  g_l4in);
    cudaGetSymbolAddress(&p_y4,    g_y4);
    cudaGetSymbolAddress(&p_l3in,  g_l3in);
    cudaGetSymbolAddress(&p_y3,    g_y3);
    cudaGetSymbolAddress(&p_l2in,  g_l2in);
    cudaGetSymbolAddress(&p_stats, g_stats);
    cudaGetSymbolAddress(&p_gn,    g_gn);
    float* x5    = (float*)p_x5;
    float* l4in  = (float*)p_l4in;
    float* y4    = (float*)p_y4;
    float* l3in  = (float*)p_l3in;
    float* y3    = (float*)p_y3;
    float* l2in  = (float*)p_l2in;
    float* stats = (float*)p_stats;
    float* gn    = (float*)p_gn;

    init_stats_kernel<<<1, 128>>>();

    // 1) x5 = feats_s5 @ W_in^T + b_in   (2048x2048x2048)
    gemm_kernel<0><<<dim3(C_IN / 128, N5v / 128), 256>>>(
        feats_s5, W_in, b_in, x5, K1v, C_IN, nullptr, nullptr, 0);

    // 2) l4in = concat(x5[up3], feats_s4)   (8192 x 3072)
    concat4_kernel<<<N4v, 256>>>(x5, up3, feats_s4, l4in);

    // 3) y4 = l4in @ W4^T + b4, with GN stats   (8192x1024x3072)
    gemm_kernel<1><<<dim3(C4v / 128, N4v / 128), 256>>>(
        l4in, W4, b4, y4, K4v, C4v, stats + 0, stats + 32, C4v / 32);
    gn_finalize_kernel<<<1, 32>>>(0);

    // 4) l3in = concat(act4(y4)[up2], feats_s3)   (32768 x 1536)
    concat_act_kernel<<<N3v, 256>>>(y4, up2, feats_s3, l3in,
                                    g4, beta4, gn + 0, gn + 32,
                                    C4v, D3v, C4v / 32);

    // 5) y3 = l3in @ W3^T + b3, with GN stats   (32768x512x1536)
    gemm_kernel<1><<<dim3(C3v / 128, N3v / 128), 256>>>(
        l3in, W3, b3, y3, K3v, C3v, stats + 64, stats + 96, C3v / 32);
    gn_finalize_kernel<<<1, 32>>>(1);

    // 6) l2in = concat(act3(y3)[up1], feats_s2)   (131072 x 768)
    concat_act_kernel<<<N2v, 256>>>(y3, up1, feats_s2, l2in,
                                    g3, beta3, gn + 64, gn + 96,
                                    C3v, D2v, C3v / 32);

    // 7) out = l2in @ W2^T + b2   (131072x256x768)
    gemm_kernel<0><<<dim3(COUTv / 128, N2v / 128), 256>>>(
        l2in, W2, b2, out, K2v, COUTv, nullptr, nullptr, 0);
}

// round 3
// speedup vs baseline: 1.9564x; 1.9564x over previous
#include <cuda_runtime.h>
#include <cstdint>

// ---------------- problem dimensions (fixed) ----------------
#define N2v 131072
#define N3v 32768
#define N4v 8192
#define N5v 2048
#define D2v 256
#define D3v 512
#define D4v 1024
#define D5v 2048
#define C_IN 2048
#define C4v 1024
#define C3v 512
#define COUTv 256
#define K1v 2048
#define K4v 3072
#define K3v 1536
#define K2v 768
#define NEG_SLOPE 0.1f
#define GN_EPS 1e-5f

// ---------------- scratch ----------------
__device__ float g_x5[(size_t)N5v * C_IN];
__device__ float g_l4in[(size_t)N4v * K4v];
__device__ float g_y4[(size_t)N4v * C4v];
__device__ float g_l3in[(size_t)N3v * K3v];
__device__ float g_y3[(size_t)N3v * C3v];
__device__ float g_l2in[(size_t)N2v * K2v];
__device__ float g_stats[128];
__device__ float g_gn[128];

__global__ void init_stats_kernel() {
    if (threadIdx.x < 128) g_stats[threadIdx.x] = 0.0f;
}

// ---------------- helpers ----------------
__device__ __forceinline__ float to_tf32(float x) {
    uint32_t u;
    asm("cvt.rna.tf32.f32 %0, %1;" : "=r"(u) : "f"(x));
    return __uint_as_float(u);
}

__device__ __forceinline__ void mma_tf32(float* c,
                                         uint32_t a0, uint32_t a1, uint32_t a2, uint32_t a3,
                                         uint32_t b0, uint32_t b1) {
    asm volatile(
        "mma.sync.aligned.m16n8k8.row.col.f32.tf32.tf32.f32 "
        "{%0,%1,%2,%3}, {%4,%5,%6,%7}, {%8,%9}, {%0,%1,%2,%3};\n"
        : "+f"(c[0]), "+f"(c[1]), "+f"(c[2]), "+f"(c[3])
        : "r"(a0), "r"(a1), "r"(a2), "r"(a3), "r"(b0), "r"(b1));
}

// ---------------- tensor-core GEMM: C(N,M) = A(N,K) @ W(M,K)^T + bias ----------------
// 128x128 block, BK=16, 8 warps in 2x4 grid, warp tile 64x32, mma m16n8k8 tf32.
template<int DO_STATS>
__global__ void __launch_bounds__(256)
gemm_tc_kernel(const float* __restrict__ A, const float* __restrict__ W,
               const float* __restrict__ bias, float* __restrict__ C,
               int K, int M,
               float* __restrict__ gsum, float* __restrict__ gss, int cpg)
{
    const int BK = 16, PAD = 136;   // 128 + 8 pad -> conflict-free fragment LDS
    __shared__ float As[BK][PAD];
    __shared__ float Ws[BK][PAD];
    __shared__ float bsum[8], bssum[8];

    const int tid = threadIdx.x;
    const int lane = tid & 31;
    const int warpId = tid >> 5;
    const int wRow = warpId >> 2;       // 0..1
    const int wCol = warpId & 3;        // 0..3
    const int mWarp = wRow * 64;
    const int nWarp = wCol * 32;
    const int g = lane >> 2;            // 0..7
    const int t = lane & 3;             // 0..3

    const long rBase = (long)blockIdx.y * 128;
    const long cBase = (long)blockIdx.x * 128;

    if (DO_STATS && tid < 8) { bsum[tid] = 0.0f; bssum[tid] = 0.0f; }

    float acc[4][4][4];
#pragma unroll
    for (int i = 0; i < 4; i++)
#pragma unroll
        for (int j = 0; j < 4; j++)
#pragma unroll
            for (int q = 0; q < 4; q++) acc[i][j][q] = 0.0f;

    const float* Aptr = A + rBase * K;
    const float* Wptr = W + cBase * K;

    for (int k0 = 0; k0 < K; k0 += BK) {
        // cooperative load + transpose to k-major smem, with tf32 rounding
#pragma unroll
        for (int j = 0; j < 2; j++) {
            int idx = tid + j * 256;   // 0..511
            int row = idx >> 2;
            int kq = idx & 3;
            float4 va = *(const float4*)(Aptr + (long)row * K + k0 + kq * 4);
            As[kq * 4 + 0][row] = to_tf32(va.x);
            As[kq * 4 + 1][row] = to_tf32(va.y);
            As[kq * 4 + 2][row] = to_tf32(va.z);
            As[kq * 4 + 3][row] = to_tf32(va.w);
            float4 vw = *(const float4*)(Wptr + (long)row * K + k0 + kq * 4);
            Ws[kq * 4 + 0][row] = to_tf32(vw.x);
            Ws[kq * 4 + 1][row] = to_tf32(vw.y);
            Ws[kq * 4 + 2][row] = to_tf32(vw.z);
            Ws[kq * 4 + 3][row] = to_tf32(vw.w);
        }
        __syncthreads();

#pragma unroll
        for (int ks = 0; ks < 2; ks++) {
            const int kb = ks * 8;
            uint32_t af[4][4], bf[4][2];
#pragma unroll
            for (int mt = 0; mt < 4; mt++) {
                int r0 = mWarp + mt * 16 + g;
                af[mt][0] = __float_as_uint(As[kb + t][r0]);
                af[mt][1] = __float_as_uint(As[kb + t][r0 + 8]);
                af[mt][2] = __float_as_uint(As[kb + t + 4][r0]);
                af[mt][3] = __float_as_uint(As[kb + t + 4][r0 + 8]);
            }
#pragma unroll
            for (int nt = 0; nt < 4; nt++) {
                int c0 = nWarp + nt * 8 + g;
                bf[nt][0] = __float_as_uint(Ws[kb + t][c0]);
                bf[nt][1] = __float_as_uint(Ws[kb + t + 4][c0]);
            }
#pragma unroll
            for (int mt = 0; mt < 4; mt++)
#pragma unroll
                for (int nt = 0; nt < 4; nt++)
                    mma_tf32(acc[mt][nt], af[mt][0], af[mt][1], af[mt][2], af[mt][3],
                             bf[nt][0], bf[nt][1]);
        }
        __syncthreads();
    }

    // ---------------- epilogue ----------------
    float s[4] = {0, 0, 0, 0}, ss[4] = {0, 0, 0, 0};
#pragma unroll
    for (int nt = 0; nt < 4; nt++) {
        long col = cBase + nWarp + nt * 8 + 2 * t;
        float b0 = bias[col], b1 = bias[col + 1];
#pragma unroll
        for (int mt = 0; mt < 4; mt++) {
            long row0 = rBase + mWarp + mt * 16 + g;
            long row1 = row0 + 8;
            float v0 = acc[mt][nt][0] + b0;
            float v1 = acc[mt][nt][1] + b1;
            float v2 = acc[mt][nt][2] + b0;
            float v3 = acc[mt][nt][3] + b1;
            *(float2*)(C + row0 * M + col) = make_float2(v0, v1);
            *(float2*)(C + row1 * M + col) = make_float2(v2, v3);
            if (DO_STATS) {
                s[nt] += v0 + v1 + v2 + v3;
                ss[nt] += v0 * v0 + v1 * v1 + v2 * v2 + v3 * v3;
            }
        }
    }

    if (DO_STATS) {
#pragma unroll
        for (int nt = 0; nt < 4; nt++) {
            float sv = s[nt], sq = ss[nt];
#pragma unroll
            for (int o = 16; o > 0; o >>= 1) {
                sv += __shfl_xor_sync(0xFFFFFFFF, sv, o);
                sq += __shfl_xor_sync(0xFFFFFFFF, sq, o);
            }
            if (lane == 0) {
                int gl = (nWarp + nt * 8) / cpg;
                atomicAdd(&bsum[gl], sv);
                atomicAdd(&bssum[gl], sq);
            }
        }
        __syncthreads();
        int gpb = 128 / cpg;
        if (tid < gpb) {
            int grp = (int)(cBase / cpg) + tid;
            atomicAdd(&gsum[grp], bsum[tid]);
            atomicAdd(&gss[grp], bssum[tid]);
        }
    }
}

// ---------------- GN finalize ----------------
__global__ void gn_finalize_kernel(int which) {
    int g = threadIdx.x;
    if (g >= 32) return;
    if (which == 0) {
        float cnt = (float)((C4v / 32) * N4v);
        float m = g_stats[g] / cnt;
        float var = g_stats[32 + g] / cnt - m * m;
        g_gn[g] = m;
        g_gn[32 + g] = rsqrtf(var + GN_EPS);
    } else {
        float cnt = (float)((C3v / 32) * N3v);
        float m = g_stats[64 + g] / cnt;
        float var = g_stats[96 + g] / cnt - m * m;
        g_gn[64 + g] = m;
        g_gn[96 + g] = rsqrtf(var + GN_EPS);
    }
}

// ---------------- gather + concat (level 4 input) ----------------
__global__ void concat4_kernel(const float* __restrict__ x5,
                               const int* __restrict__ up3,
                               const float* __restrict__ f4,
                               float* __restrict__ out)
{
    int r = blockIdx.x;
    int src = up3[r];
    const float4* a = (const float4*)(x5 + (long)src * C_IN);
    const float4* b = (const float4*)(f4 + (long)r * D4v);
    float4* o = (float4*)(out + (long)r * K4v);
    const int QA = C_IN / 4, QT = K4v / 4;
    for (int c = threadIdx.x; c < QT; c += blockDim.x)
        o[c] = (c < QA) ? a[c] : b[c - QA];
}

// ---------------- gather + GN + LeakyReLU + concat ----------------
__global__ void concat_act_kernel(const float* __restrict__ y,
                                  const int* __restrict__ up,
                                  const float* __restrict__ f,
                                  float* __restrict__ out,
                                  const float* __restrict__ gamma,
                                  const float* __restrict__ beta,
                                  const float* __restrict__ gnMean,
                                  const float* __restrict__ gnInv,
                                  int Cy, int Cf, int cpg)
{
    int r = blockIdx.x;
    int src = up[r];
    int Ktot = Cy + Cf;
    const float* yrow = y + (long)src * Cy;
    const float* frow = f + (long)r * Cf;
    float* orow = out + (long)r * Ktot;
    for (int c4 = threadIdx.x; c4 < Ktot / 4; c4 += blockDim.x) {
        int c = c4 * 4;
        float4 v;
        if (c < Cy) {
            v = *(const float4*)(yrow + c);
            int g = c / cpg;
            float m = gnMean[g], inv = gnInv[g];
            float vals[4] = {v.x, v.y, v.z, v.w};
#pragma unroll
            for (int q = 0; q < 4; q++) {
                float u = (vals[q] - m) * inv * gamma[c + q] + beta[c + q];
                vals[q] = (u > 0.0f) ? u : u * NEG_SLOPE;
            }
            v = make_float4(vals[0], vals[1], vals[2], vals[3]);
        } else {
            v = *(const float4*)(frow + (c - Cy));
        }
        *(float4*)(orow + c) = v;
    }
}

// ---------------- launch ----------------
extern "C" void kernel_launch(void* const* d_in, const int* in_sizes, int n_in,
                              void* d_out, int out_size)
{
    (void)in_sizes; (void)n_in; (void)out_size;
    const float* feats_s2 = (const float*)d_in[0];
    const float* feats_s3 = (const float*)d_in[1];
    const float* feats_s4 = (const float*)d_in[2];
    const float* feats_s5 = (const float*)d_in[3];
    const int*   up1      = (const int*)d_in[4];
    const int*   up2      = (const int*)d_in[5];
    const int*   up3      = (const int*)d_in[6];
    const float* W_in     = (const float*)d_in[7];
    const float* b_in     = (const float*)d_in[8];
    const float* W4       = (const float*)d_in[9];
    const float* b4       = (const float*)d_in[10];
    const float* g4       = (const float*)d_in[11];
    const float* beta4    = (const float*)d_in[12];
    const float* W3       = (const float*)d_in[13];
    const float* b3       = (const float*)d_in[14];
    const float* g3       = (const float*)d_in[15];
    const float* beta3    = (const float*)d_in[16];
    const float* W2       = (const float*)d_in[17];
    const float* b2       = (const float*)d_in[18];
    float* out = (float*)d_out;

    void *p_x5, *p_l4in, *p_y4, *p_l3in, *p_y3, *p_l2in, *p_stats, *p_gn;
    cudaGetSymbolAddress(&p_x5,    g_x5);
    cudaGetSymbolAddress(&p_l4in,  g_l4in);
    cudaGetSymbolAddress(&p_y4,    g_y4);
    cudaGetSymbolAddress(&p_l3in,  g_l3in);
    cudaGetSymbolAddress(&p_y3,    g_y3);
    cudaGetSymbolAddress(&p_l2in,  g_l2in);
    cudaGetSymbolAddress(&p_stats, g_stats);
    cudaGetSymbolAddress(&p_gn,    g_gn);
    float* x5    = (float*)p_x5;
    float* l4in  = (float*)p_l4in;
    float* y4    = (float*)p_y4;
    float* l3in  = (float*)p_l3in;
    float* y3    = (float*)p_y3;
    float* l2in  = (float*)p_l2in;
    float* stats = (float*)p_stats;
    float* gn    = (float*)p_gn;

    init_stats_kernel<<<1, 128>>>();

    // 1) x5 = feats_s5 @ W_in^T + b_in
    gemm_tc_kernel<0><<<dim3(C_IN / 128, N5v / 128), 256>>>(
        feats_s5, W_in, b_in, x5, K1v, C_IN, nullptr, nullptr, 1);

    // 2) l4in = concat(x5[up3], feats_s4)
    concat4_kernel<<<N4v, 256>>>(x5, up3, feats_s4, l4in);

    // 3) y4 = l4in @ W4^T + b4, fused GN stats
    gemm_tc_kernel<1><<<dim3(C4v / 128, N4v / 128), 256>>>(
        l4in, W4, b4, y4, K4v, C4v, stats + 0, stats + 32, C4v / 32);
    gn_finalize_kernel<<<1, 32>>>(0);

    // 4) l3in = concat(act4(y4)[up2], feats_s3)
    concat_act_kernel<<<N3v, 256>>>(y4, up2, feats_s3, l3in,
                                    g4, beta4, gn + 0, gn + 32,
                                    C4v, D3v, C4v / 32);

    // 5) y3 = l3in @ W3^T + b3, fused GN stats
    gemm_tc_kernel<1><<<dim3(C3v / 128, N3v / 128), 256>>>(
        l3in, W3, b3, y3, K3v, C3v, stats + 64, stats + 96, C3v / 32);
    gn_finalize_kernel<<<1, 32>>>(1);

    // 6) l2in = concat(act3(y3)[up1], feats_s2)
    concat_act_kernel<<<N2v, 256>>>(y3, up1, feats_s2, l2in,
                                    g3, beta3, gn + 64, gn + 96,
                                    C3v, D2v, C3v / 32);

    // 7) out = l2in @ W2^T + b2
    gemm_tc_kernel<0><<<dim3(COUTv / 128, N2v / 128), 256>>>(
        l2in, W2, b2, out, K2v, COUTv, nullptr, nullptr, 1);
}

// round 8
// speedup vs baseline: 2.3801x; 1.2165x over previous
#include <cuda_runtime.h>
#include <cstdint>

// ---------------- problem dimensions (fixed) ----------------
#define N2v 131072
#define N3v 32768
#define N4v 8192
#define N5v 2048
#define D2v 256
#define D3v 512
#define D4v 1024
#define D5v 2048
#define C_IN 2048
#define C4v 1024
#define C3v 512
#define COUTv 256
#define K1v 2048
#define K4v 3072
#define K3v 1536
#define K2v 768
#define NEG_SLOPE 0.1f
#define GN_EPS 1e-5f

// ---------------- scratch ----------------
__device__ float g_x5[(size_t)N5v * C_IN];
__device__ float g_l4in[(size_t)N4v * K4v];
__device__ float g_y4[(size_t)N4v * C4v];
__device__ float g_l3in[(size_t)N3v * K3v];
__device__ float g_y3[(size_t)N3v * C3v];
__device__ float g_l2in[(size_t)N2v * K2v];
__device__ float g_stats[128];
__device__ float g_gn[128];

__global__ void init_stats_kernel() {
    if (threadIdx.x < 128) g_stats[threadIdx.x] = 0.0f;
}

// ---------------- helpers ----------------
__device__ __forceinline__ float to_tf32(float x) {
    uint32_t u;
    asm("cvt.rna.tf32.f32 %0, %1;" : "=r"(u) : "f"(x));
    return __uint_as_float(u);
}

__device__ __forceinline__ void mma_tf32(float* c,
                                         uint32_t a0, uint32_t a1, uint32_t a2, uint32_t a3,
                                         uint32_t b0, uint32_t b1) {
    asm volatile(
        "mma.sync.aligned.m16n8k8.row.col.f32.tf32.tf32.f32 "
        "{%0,%1,%2,%3}, {%4,%5,%6,%7}, {%8,%9}, {%0,%1,%2,%3};\n"
        : "+f"(c[0]), "+f"(c[1]), "+f"(c[2]), "+f"(c[3])
        : "r"(a0), "r"(a1), "r"(a2), "r"(a3), "r"(b0), "r"(b1));
}

// cooperative tile load: 128x16 floats, 128 threads, 4 float4 each
__device__ __forceinline__ void ldg_t(float4* r, const float* __restrict__ p,
                                      int K, int k0, int tid) {
#pragma unroll
    for (int ld = 0; ld < 4; ld++) {
        int idx = ld * 128 + tid;     // 0..511
        int row = idx >> 2;           // 0..127
        int kq = idx & 3;             // float4 slot within 16-wide K chunk
        r[ld] = *(const float4*)(p + (long)row * K + k0 + kq * 4);
    }
}
// transpose to k-major smem with tf32 rounding
__device__ __forceinline__ void sts_t(const float4* r, float (*S)[136], int tid) {
#pragma unroll
    for (int ld = 0; ld < 4; ld++) {
        int idx = ld * 128 + tid;
        int row = idx >> 2;
        int kq = idx & 3;
        S[kq * 4 + 0][row] = to_tf32(r[ld].x);
        S[kq * 4 + 1][row] = to_tf32(r[ld].y);
        S[kq * 4 + 2][row] = to_tf32(r[ld].z);
        S[kq * 4 + 3][row] = to_tf32(r[ld].w);
    }
}

// ---------------- tensor-core GEMM: C(N,M) = A(N,K) @ W(M,K)^T + bias ----------------
// 128x128 block, BK=16, 4 warps in 2x2 grid, warp tile 64x64, double-buffered smem.
template<int DO_STATS>
__global__ void __launch_bounds__(128)
gemm_tc_kernel(const float* __restrict__ A, const float* __restrict__ W,
               const float* __restrict__ bias, float* __restrict__ C,
               int K, int M,
               float* __restrict__ gsum, float* __restrict__ gss, int cpg)
{
    __shared__ float As[2][16][136];    // +8 pad -> conflict-free fragment LDS
    __shared__ float Ws[2][16][136];
    __shared__ float bsum[8], bssum[8];

    const int tid = threadIdx.x;
    const int lane = tid & 31;
    const int warpId = tid >> 5;        // 0..3
    const int wRow = warpId >> 1;       // 0..1
    const int wCol = warpId & 1;        // 0..1
    const int mWarp = wRow * 64;
    const int nWarp = wCol * 64;
    const int g = lane >> 2;            // 0..7
    const int t = lane & 3;             // 0..3

    const long rBase = (long)blockIdx.y * 128;
    const long cBase = (long)blockIdx.x * 128;

    if (DO_STATS && tid < 8) { bsum[tid] = 0.0f; bssum[tid] = 0.0f; }

    float acc[4][8][4];
#pragma unroll
    for (int i = 0; i < 4; i++)
#pragma unroll
        for (int j = 0; j < 8; j++)
#pragma unroll
            for (int q = 0; q < 4; q++) acc[i][j][q] = 0.0f;

    const float* Aptr = A + rBase * K;
    const float* Wptr = W + cBase * K;
    const int nIter = K >> 4;

    float4 rA[4], rB[4];
    ldg_t(rA, Aptr, K, 0, tid);
    ldg_t(rB, Wptr, K, 0, tid);
    sts_t(rA, As[0], tid);
    sts_t(rB, Ws[0], tid);
    __syncthreads();

    for (int it = 0; it < nIter; ++it) {
        const int cur = it & 1;
        const bool more = (it + 1 < nIter);
        // prefetch next tile (LDG latency hidden behind the mma phase)
        if (more) {
            ldg_t(rA, Aptr, K, (it + 1) * 16, tid);
            ldg_t(rB, Wptr, K, (it + 1) * 16, tid);
        }
        // mma phase on current buffer
#pragma unroll
        for (int ks = 0; ks < 2; ks++) {
            const int kb = ks * 8;
            uint32_t af[4][4], bf[8][2];
#pragma unroll
            for (int mt = 0; mt < 4; mt++) {
                int r0 = mWarp + mt * 16 + g;
                af[mt][0] = __float_as_uint(As[cur][kb + t][r0]);
                af[mt][1] = __float_as_uint(As[cur][kb + t][r0 + 8]);
                af[mt][2] = __float_as_uint(As[cur][kb + t + 4][r0]);
                af[mt][3] = __float_as_uint(As[cur][kb + t + 4][r0 + 8]);
            }
#pragma unroll
            for (int nt = 0; nt < 8; nt++) {
                int c0 = nWarp + nt * 8 + g;
                bf[nt][0] = __float_as_uint(Ws[cur][kb + t][c0]);
                bf[nt][1] = __float_as_uint(Ws[cur][kb + t + 4][c0]);
            }
#pragma unroll
            for (int mt = 0; mt < 4; mt++)
#pragma unroll
                for (int nt = 0; nt < 8; nt++)
                    mma_tf32(acc[mt][nt], af[mt][0], af[mt][1], af[mt][2], af[mt][3],
                             bf[nt][0], bf[nt][1]);
        }
        // store next tile into the other buffer
        if (more) {
            sts_t(rA, As[cur ^ 1], tid);
            sts_t(rB, Ws[cur ^ 1], tid);
        }
        __syncthreads();
    }

    // ---------------- epilogue ----------------
    float s[8], ss[8];
#pragma unroll
    for (int q = 0; q < 8; q++) { s[q] = 0.0f; ss[q] = 0.0f; }

#pragma unroll
    for (int nt = 0; nt < 8; nt++) {
        long col = cBase + nWarp + nt * 8 + 2 * t;
        float b0 = bias[col], b1 = bias[col + 1];
#pragma unroll
        for (int mt = 0; mt < 4; mt++) {
            long row0 = rBase + mWarp + mt * 16 + g;
            long row1 = row0 + 8;
            float v0 = acc[mt][nt][0] + b0;
            float v1 = acc[mt][nt][1] + b1;
            float v2 = acc[mt][nt][2] + b0;
            float v3 = acc[mt][nt][3] + b1;
            *(float2*)(C + row0 * M + col) = make_float2(v0, v1);
            *(float2*)(C + row1 * M + col) = make_float2(v2, v3);
            if (DO_STATS) {
                s[nt] += v0 + v1 + v2 + v3;
                ss[nt] += v0 * v0 + v1 * v1 + v2 * v2 + v3 * v3;
            }
        }
    }

    if (DO_STATS) {
        const int shift = (cpg == 32) ? 5 : 4;
#pragma unroll
        for (int nt = 0; nt < 8; nt++) {
            float sv = s[nt], sq = ss[nt];
#pragma unroll
            for (int o = 16; o > 0; o >>= 1) {
                sv += __shfl_xor_sync(0xFFFFFFFF, sv, o);
                sq += __shfl_xor_sync(0xFFFFFFFF, sq, o);
            }
            if (lane == 0) {
                int gl = (nWarp + nt * 8) >> shift;
                atomicAdd(&bsum[gl], sv);
                atomicAdd(&bssum[gl], sq);
            }
        }
        __syncthreads();
        int gpb = 128 >> shift;
        if (tid < gpb) {
            int grp = (int)(cBase >> shift) + tid;
            atomicAdd(&gsum[grp], bsum[tid]);
            atomicAdd(&gss[grp], bssum[tid]);
        }
    }
}

// ---------------- GN finalize ----------------
__global__ void gn_finalize_kernel(int which) {
    int g = threadIdx.x;
    if (g >= 32) return;
    if (which == 0) {
        float cnt = (float)((C4v / 32) * N4v);
        float m = g_stats[g] / cnt;
        float var = g_stats[32 + g] / cnt - m * m;
        g_gn[g] = m;
        g_gn[32 + g] = rsqrtf(var + GN_EPS);
    } else {
        float cnt = (float)((C3v / 32) * N3v);
        float m = g_stats[64 + g] / cnt;
        float var = g_stats[96 + g] / cnt - m * m;
        g_gn[64 + g] = m;
        g_gn[96 + g] = rsqrtf(var + GN_EPS);
    }
}

// ---------------- gather + concat (level 4 input) ----------------
__global__ void concat4_kernel(const float* __restrict__ x5,
                               const int* __restrict__ up3,
                               const float* __restrict__ f4,
                               float* __restrict__ out)
{
    int r = blockIdx.x;
    int src = up3[r];
    const float4* a = (const float4*)(x5 + (long)src * C_IN);
    const float4* b = (const float4*)(f4 + (long)r * D4v);
    float4* o = (float4*)(out + (long)r * K4v);
    const int QA = C_IN / 4, QT = K4v / 4;
    for (int c = threadIdx.x; c < QT; c += blockDim.x)
        o[c] = (c < QA) ? a[c] : b[c - QA];
}

// ---------------- gather + GN + LeakyReLU + concat ----------------
__global__ void concat_act_kernel(const float* __restrict__ y,
                                  const int* __restrict__ up,
                                  const float* __restrict__ f,
                                  float* __restrict__ out,
                                  const float* __restrict__ gamma,
                                  const float* __restrict__ beta,
                                  const float* __restrict__ gnMean,
                                  const float* __restrict__ gnInv,
                                  int Cy, int Cf, int cpg)
{
    int r = blockIdx.x;
    int src = up[r];
    int Ktot = Cy + Cf;
    const float* yrow = y + (long)src * Cy;
    const float* frow = f + (long)r * Cf;
    float* orow = out + (long)r * Ktot;
    for (int c4 = threadIdx.x; c4 < Ktot / 4; c4 += blockDim.x) {
        int c = c4 * 4;
        float4 v;
        if (c < Cy) {
            v = *(const float4*)(yrow + c);
            int g = c / cpg;
            float m = gnMean[g], inv = gnInv[g];
            float vals[4] = {v.x, v.y, v.z, v.w};
#pragma unroll
            for (int q = 0; q < 4; q++) {
                float u = (vals[q] - m) * inv * gamma[c + q] + beta[c + q];
                vals[q] = (u > 0.0f) ? u : u * NEG_SLOPE;
            }
            v = make_float4(vals[0], vals[1], vals[2], vals[3]);
        } else {
            v = *(const float4*)(frow + (c - Cy));
        }
        *(float4*)(orow + c) = v;
    }
}

// ---------------- launch ----------------
extern "C" void kernel_launch(void* const* d_in, const int* in_sizes, int n_in,
                              void* d_out, int out_size)
{
    (void)in_sizes; (void)n_in; (void)out_size;
    const float* feats_s2 = (const float*)d_in[0];
    const float* feats_s3 = (const float*)d_in[1];
    const float* feats_s4 = (const float*)d_in[2];
    const float* feats_s5 = (const float*)d_in[3];
    const int*   up1      = (const int*)d_in[4];
    const int*   up2      = (const int*)d_in[5];
    const int*   up3      = (const int*)d_in[6];
    const float* W_in     = (const float*)d_in[7];
    const float* b_in     = (const float*)d_in[8];
    const float* W4       = (const float*)d_in[9];
    const float* b4       = (const float*)d_in[10];
    const float* g4       = (const float*)d_in[11];
    const float* beta4    = (const float*)d_in[12];
    const float* W3       = (const float*)d_in[13];
    const float* b3       = (const float*)d_in[14];
    const float* g3       = (const float*)d_in[15];
    const float* beta3    = (const float*)d_in[16];
    const float* W2       = (const float*)d_in[17];
    const float* b2       = (const float*)d_in[18];
    float* out = (float*)d_out;

    void *p_x5, *p_l4in, *p_y4, *p_l3in, *p_y3, *p_l2in, *p_stats, *p_gn;
    cudaGetSymbolAddress(&p_x5,    g_x5);
    cudaGetSymbolAddress(&p_l4in,  g_l4in);
    cudaGetSymbolAddress(&p_y4,    g_y4);
    cudaGetSymbolAddress(&p_l3in,  g_l3in);
    cudaGetSymbolAddress(&p_y3,    g_y3);
    cudaGetSymbolAddress(&p_l2in,  g_l2in);
    cudaGetSymbolAddress(&p_stats, g_stats);
    cudaGetSymbolAddress(&p_gn,    g_gn);
    float* x5    = (float*)p_x5;
    float* l4in  = (float*)p_l4in;
    float* y4    = (float*)p_y4;
    float* l3in  = (float*)p_l3in;
    float* y3    = (float*)p_y3;
    float* l2in  = (float*)p_l2in;
    float* stats = (float*)p_stats;
    float* gn    = (float*)p_gn;

    init_stats_kernel<<<1, 128>>>();

    // 1) x5 = feats_s5 @ W_in^T + b_in   (2048 x 2048 x K=2048)
    gemm_tc_kernel<0><<<dim3(C_IN / 128, N5v / 128), 128>>>(
        feats_s5, W_in, b_in, x5, K1v, C_IN, nullptr, nullptr, 32);

    // 2) l4in = concat(x5[up3], feats_s4)
    concat4_kernel<<<N4v, 256>>>(x5, up3, feats_s4, l4in);

    // 3) y4 = l4in @ W4^T + b4, fused GN stats   (8192 x 1024 x K=3072)
    gemm_tc_kernel<1><<<dim3(C4v / 128, N4v / 128), 128>>>(
        l4in, W4, b4, y4, K4v, C4v, stats + 0, stats + 32, C4v / 32);
    gn_finalize_kernel<<<1, 32>>>(0);

    // 4) l3in = concat(act4(y4)[up2], feats_s3)
    concat_act_kernel<<<N3v, 256>>>(y4, up2, feats_s3, l3in,
                                    g4, beta4, gn + 0, gn + 32,
                                    C4v, D3v, C4v / 32);

    // 5) y3 = l3in @ W3^T + b3, fused GN stats   (32768 x 512 x K=1536)
    gemm_tc_kernel<1><<<dim3(C3v / 128, N3v / 128), 128>>>(
        l3in, W3, b3, y3, K3v, C3v, stats + 64, stats + 96, C3v / 32);
    gn_finalize_kernel<<<1, 32>>>(1);

    // 6) l2in = concat(act3(y3)[up1], feats_s2)
    concat_act_kernel<<<N2v, 256>>>(y3, up1, feats_s2, l2in,
                                    g3, beta3, gn + 64, gn + 96,
                                    C3v, D2v, C3v / 32);

    // 7) out = l2in @ W2^T + b2   (131072 x 256 x K=768)
    gemm_tc_kernel<0><<<dim3(COUTv / 128, N2v / 128), 128>>>(
        l2in, W2, b2, out, K2v, COUTv, nullptr, nullptr, 32);
}

// round 13
// speedup vs baseline: 2.8536x; 1.1989x over previous
#include <cuda_runtime.h>
#include <cstdint>

// ---------------- problem dimensions (fixed) ----------------
#define N2v 131072
#define N3v 32768
#define N4v 8192
#define N5v 2048
#define D2v 256
#define D3v 512
#define D4v 1024
#define D5v 2048
#define C_IN 2048
#define C4v 1024
#define C3v 512
#define COUTv 256
#define K1v 2048
#define K4v 3072
#define K3v 1536
#define K2v 768
#define NEG_SLOPE 0.1f
#define GN_EPS 1e-5f

// ---------------- scratch ----------------
__device__ float g_x5[(size_t)N5v * C_IN];
__device__ float g_l4in[(size_t)N4v * K4v];
__device__ float g_y4[(size_t)N4v * C4v];
__device__ float g_l3in[(size_t)N3v * K3v];
__device__ float g_y3[(size_t)N3v * C3v];
__device__ float g_l2in[(size_t)N2v * K2v];
__device__ float g_stats[128];
__device__ float g_gn[128];

__global__ void init_stats_kernel() {
    if (threadIdx.x < 128) g_stats[threadIdx.x] = 0.0f;
}

// ---------------- helpers ----------------
__device__ __forceinline__ float to_tf32(float x) {
    uint32_t u;
    asm("cvt.rna.tf32.f32 %0, %1;" : "=r"(u) : "f"(x));
    return __uint_as_float(u);
}

__device__ __forceinline__ void mma_tf32(float* c,
                                         uint32_t a0, uint32_t a1, uint32_t a2, uint32_t a3,
                                         uint32_t b0, uint32_t b1) {
    asm volatile(
        "mma.sync.aligned.m16n8k8.row.col.f32.tf32.tf32.f32 "
        "{%0,%1,%2,%3}, {%4,%5,%6,%7}, {%8,%9}, {%0,%1,%2,%3};\n"
        : "+f"(c[0]), "+f"(c[1]), "+f"(c[2]), "+f"(c[3])
        : "r"(a0), "r"(a1), "r"(a2), "r"(a3), "r"(b0), "r"(b1));
}

// cooperative tile load: 128 rows x 16 k floats, 128 threads, 4 float4 each
__device__ __forceinline__ void ldg_t(float4* r, const float* __restrict__ p,
                                      int K, int k0, int tid) {
#pragma unroll
    for (int ld = 0; ld < 4; ld++) {
        int idx = ld * 128 + tid;     // 0..511
        int row = idx >> 2;           // 0..127
        int kq = idx & 3;             // float4 slot within 16-wide K chunk
        r[ld] = *(const float4*)(p + (long)row * K + k0 + kq * 4);
    }
}
// m-major tile store, XOR-swizzled k: addr = row*16 + (k ^ ((row&6)*2)).
// Swizzle value is a multiple of 4 -> thread's float4 stays contiguous (STS.128),
// and per 8-lane phase all quad-banks are distinct (conflict-free).
__device__ __forceinline__ void sts_t(const float4* r, float* S, int tid) {
    const int rbase = tid >> 2;                   // 0..31
    const int ksw = ((tid & 3) * 4) ^ ((rbase & 6) * 2);  // row&6 == rbase&6 for all ld
#pragma unroll
    for (int ld = 0; ld < 4; ld++) {
        int row = ld * 32 + rbase;
        float4 v;
        v.x = to_tf32(r[ld].x);
        v.y = to_tf32(r[ld].y);
        v.z = to_tf32(r[ld].z);
        v.w = to_tf32(r[ld].w);
        *(float4*)&S[row * 16 + ksw] = v;
    }
}

// ---------------- tensor-core GEMM: C(N,M) = A(N,K) @ W(M,K)^T + bias ----------------
// 128x128 block, BK=16, 4 warps in 2x2 grid, warp tile 64x64, double-buffered smem,
// m-major XOR-swizzled tiles (conflict-free STS.128 writes and fragment reads).
template<int DO_STATS>
__global__ void __launch_bounds__(128)
gemm_tc_kernel(const float* __restrict__ A, const float* __restrict__ W,
               const float* __restrict__ bias, float* __restrict__ C,
               int K, int M,
               float* __restrict__ gsum, float* __restrict__ gss, int cpg)
{
    __shared__ float As[2][128 * 16];
    __shared__ float Ws[2][128 * 16];
    __shared__ float bsum[8], bssum[8];

    const int tid = threadIdx.x;
    const int lane = tid & 31;
    const int warpId = tid >> 5;        // 0..3
    const int wRow = warpId >> 1;       // 0..1
    const int wCol = warpId & 1;        // 0..1
    const int mWarp = wRow * 64;
    const int nWarp = wCol * 64;
    const int g = lane >> 2;            // 0..7
    const int t = lane & 3;             // 0..3
    const int fsw = (g & 6) * 2;        // per-thread swizzle XOR for fragment reads

    const long rBase = (long)blockIdx.y * 128;
    const long cBase = (long)blockIdx.x * 128;

    if (DO_STATS && tid < 8) { bsum[tid] = 0.0f; bssum[tid] = 0.0f; }

    float acc[4][8][4];
#pragma unroll
    for (int i = 0; i < 4; i++)
#pragma unroll
        for (int j = 0; j < 8; j++)
#pragma unroll
            for (int q = 0; q < 4; q++) acc[i][j][q] = 0.0f;

    const float* Aptr = A + rBase * K;
    const float* Wptr = W + cBase * K;
    const int nIter = K >> 4;

    float4 rA[4], rB[4];
    ldg_t(rA, Aptr, K, 0, tid);
    ldg_t(rB, Wptr, K, 0, tid);
    sts_t(rA, As[0], tid);
    sts_t(rB, Ws[0], tid);
    __syncthreads();

    for (int it = 0; it < nIter; ++it) {
        const int cur = it & 1;
        const bool more = (it + 1 < nIter);
        // prefetch next tile (LDG latency hidden behind the mma phase)
        if (more) {
            ldg_t(rA, Aptr, K, (it + 1) * 16, tid);
            ldg_t(rB, Wptr, K, (it + 1) * 16, tid);
        }
        const float* SA = As[cur];
        const float* SW = Ws[cur];
        // mma phase on current buffer
#pragma unroll
        for (int ks = 0; ks < 2; ks++) {
            const int kb = ks * 8;
            const int kl = (kb + t) ^ fsw;        // swizzled k for a0/b0
            const int kh = (kb + t + 4) ^ fsw;    // swizzled k for a2/b1
            uint32_t af[4][4], bf[8][2];
#pragma unroll
            for (int mt = 0; mt < 4; mt++) {
                int r0 = mWarp + mt * 16 + g;
                af[mt][0] = __float_as_uint(SA[r0 * 16 + kl]);
                af[mt][1] = __float_as_uint(SA[(r0 + 8) * 16 + kl]);
                af[mt][2] = __float_as_uint(SA[r0 * 16 + kh]);
                af[mt][3] = __float_as_uint(SA[(r0 + 8) * 16 + kh]);
            }
#pragma unroll
            for (int nt = 0; nt < 8; nt++) {
                int c0 = nWarp + nt * 8 + g;
                bf[nt][0] = __float_as_uint(SW[c0 * 16 + kl]);
                bf[nt][1] = __float_as_uint(SW[c0 * 16 + kh]);
            }
#pragma unroll
            for (int mt = 0; mt < 4; mt++)
#pragma unroll
                for (int nt = 0; nt < 8; nt++)
                    mma_tf32(acc[mt][nt], af[mt][0], af[mt][1], af[mt][2], af[mt][3],
                             bf[nt][0], bf[nt][1]);
        }
        // store next tile into the other buffer
        if (more) {
            sts_t(rA, As[cur ^ 1], tid);
            sts_t(rB, Ws[cur ^ 1], tid);
        }
        __syncthreads();
    }

    // ---------------- epilogue ----------------
    float s[8], ss[8];
#pragma unroll
    for (int q = 0; q < 8; q++) { s[q] = 0.0f; ss[q] = 0.0f; }

#pragma unroll
    for (int nt = 0; nt < 8; nt++) {
        long col = cBase + nWarp + nt * 8 + 2 * t;
        float b0 = bias[col], b1 = bias[col + 1];
#pragma unroll
        for (int mt = 0; mt < 4; mt++) {
            long row0 = rBase + mWarp + mt * 16 + g;
            long row1 = row0 + 8;
            float v0 = acc[mt][nt][0] + b0;
            float v1 = acc[mt][nt][1] + b1;
            float v2 = acc[mt][nt][2] + b0;
            float v3 = acc[mt][nt][3] + b1;
            *(float2*)(C + row0 * M + col) = make_float2(v0, v1);
            *(float2*)(C + row1 * M + col) = make_float2(v2, v3);
            if (DO_STATS) {
                s[nt] += v0 + v1 + v2 + v3;
                ss[nt] += v0 * v0 + v1 * v1 + v2 * v2 + v3 * v3;
            }
        }
    }

    if (DO_STATS) {
        const int shift = (cpg == 32) ? 5 : 4;
#pragma unroll
        for (int nt = 0; nt < 8; nt++) {
            float sv = s[nt], sq = ss[nt];
#pragma unroll
            for (int o = 16; o > 0; o >>= 1) {
                sv += __shfl_xor_sync(0xFFFFFFFF, sv, o);
                sq += __shfl_xor_sync(0xFFFFFFFF, sq, o);
            }
            if (lane == 0) {
                int gl = (nWarp + nt * 8) >> shift;
                atomicAdd(&bsum[gl], sv);
                atomicAdd(&bssum[gl], sq);
            }
        }
        __syncthreads();
        int gpb = 128 >> shift;
        if (tid < gpb) {
            int grp = (int)(cBase >> shift) + tid;
            atomicAdd(&gsum[grp], bsum[tid]);
            atomicAdd(&gss[grp], bssum[tid]);
        }
    }
}

// ---------------- GN finalize ----------------
__global__ void gn_finalize_kernel(int which) {
    int g = threadIdx.x;
    if (g >= 32) return;
    if (which == 0) {
        float cnt = (float)((C4v / 32) * N4v);
        float m = g_stats[g] / cnt;
        float var = g_stats[32 + g] / cnt - m * m;
        g_gn[g] = m;
        g_gn[32 + g] = rsqrtf(var + GN_EPS);
    } else {
        float cnt = (float)((C3v / 32) * N3v);
        float m = g_stats[64 + g] / cnt;
        float var = g_stats[96 + g] / cnt - m * m;
        g_gn[64 + g] = m;
        g_gn[96 + g] = rsqrtf(var + GN_EPS);
    }
}

// ---------------- gather + concat (level 4 input) ----------------
__global__ void concat4_kernel(const float* __restrict__ x5,
                               const int* __restrict__ up3,
                               const float* __restrict__ f4,
                               float* __restrict__ out)
{
    int r = blockIdx.x;
    int src = up3[r];
    const float4* a = (const float4*)(x5 + (long)src * C_IN);
    const float4* b = (const float4*)(f4 + (long)r * D4v);
    float4* o = (float4*)(out + (long)r * K4v);
    const int QA = C_IN / 4, QT = K4v / 4;
    for (int c = threadIdx.x; c < QT; c += blockDim.x)
        o[c] = (c < QA) ? a[c] : b[c - QA];
}

// ---------------- gather + GN + LeakyReLU + concat ----------------
__global__ void concat_act_kernel(const float* __restrict__ y,
                                  const int* __restrict__ up,
                                  const float* __restrict__ f,
                                  float* __restrict__ out,
                                  const float* __restrict__ gamma,
                                  const float* __restrict__ beta,
                                  const float* __restrict__ gnMean,
                                  const float* __restrict__ gnInv,
                                  int Cy, int Cf, int cpg)
{
    int r = blockIdx.x;
    int src = up[r];
    int Ktot = Cy + Cf;
    const float* yrow = y + (long)src * Cy;
    const float* frow = f + (long)r * Cf;
    float* orow = out + (long)r * Ktot;
    for (int c4 = threadIdx.x; c4 < Ktot / 4; c4 += blockDim.x) {
        int c = c4 * 4;
        float4 v;
        if (c < Cy) {
            v = *(const float4*)(yrow + c);
            int g = c / cpg;
            float m = gnMean[g], inv = gnInv[g];
            float vals[4] = {v.x, v.y, v.z, v.w};
#pragma unroll
            for (int q = 0; q < 4; q++) {
                float u = (vals[q] - m) * inv * gamma[c + q] + beta[c + q];
                vals[q] = (u > 0.0f) ? u : u * NEG_SLOPE;
            }
            v = make_float4(vals[0], vals[1], vals[2], vals[3]);
        } else {
            v = *(const float4*)(frow + (c - Cy));
        }
        *(float4*)(orow + c) = v;
    }
}

// ---------------- launch ----------------
extern "C" void kernel_launch(void* const* d_in, const int* in_sizes, int n_in,
                              void* d_out, int out_size)
{
    (void)in_sizes; (void)n_in; (void)out_size;
    const float* feats_s2 = (const float*)d_in[0];
    const float* feats_s3 = (const float*)d_in[1];
    const float* feats_s4 = (const float*)d_in[2];
    const float* feats_s5 = (const float*)d_in[3];
    const int*   up1      = (const int*)d_in[4];
    const int*   up2      = (const int*)d_in[5];
    const int*   up3      = (const int*)d_in[6];
    const float* W_in     = (const float*)d_in[7];
    const float* b_in     = (const float*)d_in[8];
    const float* W4       = (const float*)d_in[9];
    const float* b4       = (const float*)d_in[10];
    const float* g4       = (const float*)d_in[11];
    const float* beta4    = (const float*)d_in[12];
    const float* W3       = (const float*)d_in[13];
    const float* b3       = (const float*)d_in[14];
    const float* g3       = (const float*)d_in[15];
    const float* beta3    = (const float*)d_in[16];
    const float* W2       = (const float*)d_in[17];
    const float* b2       = (const float*)d_in[18];
    float* out = (float*)d_out;

    void *p_x5, *p_l4in, *p_y4, *p_l3in, *p_y3, *p_l2in, *p_stats, *p_gn;
    cudaGetSymbolAddress(&p_x5,    g_x5);
    cudaGetSymbolAddress(&p_l4in,  g_l4in);
    cudaGetSymbolAddress(&p_y4,    g_y4);
    cudaGetSymbolAddress(&p_l3in,  g_l3in);
    cudaGetSymbolAddress(&p_y3,    g_y3);
    cudaGetSymbolAddress(&p_l2in,  g_l2in);
    cudaGetSymbolAddress(&p_stats, g_stats);
    cudaGetSymbolAddress(&p_gn,    g_gn);
    float* x5    = (float*)p_x5;
    float* l4in  = (float*)p_l4in;
    float* y4    = (float*)p_y4;
    float* l3in  = (float*)p_l3in;
    float* y3    = (float*)p_y3;
    float* l2in  = (float*)p_l2in;
    float* stats = (float*)p_stats;
    float* gn    = (float*)p_gn;

    init_stats_kernel<<<1, 128>>>();

    // 1) x5 = feats_s5 @ W_in^T + b_in   (2048 x 2048 x K=2048)
    gemm_tc_kernel<0><<<dim3(C_IN / 128, N5v / 128), 128>>>(
        feats_s5, W_in, b_in, x5, K1v, C_IN, nullptr, nullptr, 32);

    // 2) l4in = concat(x5[up3], feats_s4)
    concat4_kernel<<<N4v, 256>>>(x5, up3, feats_s4, l4in);

    // 3) y4 = l4in @ W4^T + b4, fused GN stats   (8192 x 1024 x K=3072)
    gemm_tc_kernel<1><<<dim3(C4v / 128, N4v / 128), 128>>>(
        l4in, W4, b4, y4, K4v, C4v, stats + 0, stats + 32, C4v / 32);
    gn_finalize_kernel<<<1, 32>>>(0);

    // 4) l3in = concat(act4(y4)[up2], feats_s3)
    concat_act_kernel<<<N3v, 256>>>(y4, up2, feats_s3, l3in,
                                    g4, beta4, gn + 0, gn + 32,
                                    C4v, D3v, C4v / 32);

    // 5) y3 = l3in @ W3^T + b3, fused GN stats   (32768 x 512 x K=1536)
    gemm_tc_kernel<1><<<dim3(C3v / 128, N3v / 128), 128>>>(
        l3in, W3, b3, y3, K3v, C3v, stats + 64, stats + 96, C3v / 32);
    gn_finalize_kernel<<<1, 32>>>(1);

    // 6) l2in = concat(act3(y3)[up1], feats_s2)
    concat_act_kernel<<<N2v, 256>>>(y3, up1, feats_s2, l2in,
                                    g3, beta3, gn + 64, gn + 96,
                                    C3v, D2v, C3v / 32);

    // 7) out = l2in @ W2^T + b2   (131072 x 256 x K=768)
    gemm_tc_kernel<0><<<dim3(COUTv / 128, N2v / 128), 128>>>(
        l2in, W2, b2, out, K2v, COUTv, nullptr, nullptr, 32);
}